// round 1
// baseline (speedup 1.0000x reference)
#include <cuda_runtime.h>
#include <cstdint>

// Problem constants (fixed by the dataset)
#define NNODES 50000
#define IN_C   512
#define HID_C  256
#define OUT_C  128

// ---------------------------------------------------------------------------
// Scratch (device globals — no allocation allowed)
// ---------------------------------------------------------------------------
__device__ float g_H1[(size_t)NNODES * HID_C];   // x @ W1
__device__ float g_A1[(size_t)NNODES * HID_C];   // aggregated layer-1 activations
__device__ float g_H2[(size_t)NNODES * OUT_C];   // A1 @ W2
__device__ float g_DEG[NNODES];
__device__ float g_DINV[NNODES];
__device__ int   g_is64;

// ---------------------------------------------------------------------------
// Edge index decoding (int64 vs int32, detected at runtime)
// ---------------------------------------------------------------------------
__device__ __forceinline__ int edge_at(const void* ei, long long i, int is64) {
    if (is64) return (int)((const long long*)ei)[i];
    return ((const int*)ei)[i];
}

__global__ void detect_kernel(const void* ei, long long maxv) {
    const long long* p = (const long long*)ei;
    int ok64 = 1;
    #pragma unroll
    for (int i = 0; i < 8; i++) {
        long long v = p[i];
        if (v < 0 || v >= maxv) ok64 = 0;
    }
    g_is64 = ok64;
}

// ---------------------------------------------------------------------------
// Degree / normalization
// ---------------------------------------------------------------------------
__global__ void zero_kernel(float* p, int n) {
    int i = blockIdx.x * blockDim.x + threadIdx.x;
    if (i < n) p[i] = 0.0f;
}

__global__ void hist_kernel(const void* ei, float* deg, int E) {
    int e = blockIdx.x * blockDim.x + threadIdx.x;
    if (e >= E) return;
    int is64 = g_is64;
    int d = edge_at(ei, (long long)E + e, is64);
    atomicAdd(&deg[d], 1.0f);
}

__global__ void dinv_kernel(const float* deg, float* dinv, int n) {
    int i = blockIdx.x * blockDim.x + threadIdx.x;
    if (i < n) dinv[i] = rsqrtf(deg[i] + 1.0f);   // +1 for self-loop
}

// ---------------------------------------------------------------------------
// Tiled fp32 GEMM: C[M,N] = A[M,K] @ B[K,N], row-major.
// BM=128, BN=64, BK=16, 256 threads, 8x4 microtile.
// Requires: K % 16 == 0, N % 64 == 0 (true for 512/256/128). M guarded.
// ---------------------------------------------------------------------------
__global__ __launch_bounds__(256) void gemm_kernel(
    const float* __restrict__ A, const float* __restrict__ B,
    float* __restrict__ C, int M, int K, int Nn)
{
    const int BM = 128, BN = 64, BK = 16, TM = 8, TN = 4;
    __shared__ float As[BK][BM];
    __shared__ float Bs[BK][BN];

    const int tid = threadIdx.x;
    const int tx = tid % (BN / TN);     // 0..15 (N dim)
    const int ty = tid / (BN / TN);     // 0..15 (M dim)
    const int rowBase = blockIdx.y * BM;
    const int colBase = blockIdx.x * BN;

    float acc[TM][TN];
    #pragma unroll
    for (int i = 0; i < TM; i++)
        #pragma unroll
        for (int j = 0; j < TN; j++) acc[i][j] = 0.0f;

    for (int k0 = 0; k0 < K; k0 += BK) {
        // Load A tile: 128x16 = 512 float4s, 2 per thread
        #pragma unroll
        for (int t = 0; t < 2; t++) {
            int id = tid + t * 256;
            int r  = id / 4;            // row in tile
            int kc = (id % 4) * 4;      // k offset
            float4 v = make_float4(0.f, 0.f, 0.f, 0.f);
            int gr = rowBase + r;
            if (gr < M)
                v = *(const float4*)&A[(long long)gr * K + k0 + kc];
            As[kc + 0][r] = v.x;
            As[kc + 1][r] = v.y;
            As[kc + 2][r] = v.z;
            As[kc + 3][r] = v.w;
        }
        // Load B tile: 16x64 = 256 float4s, 1 per thread
        {
            int id = tid;
            int r = id / 16;            // k row
            int c = (id % 16) * 4;      // n col
            float4 v = *(const float4*)&B[(long long)(k0 + r) * Nn + colBase + c];
            *(float4*)&Bs[r][c] = v;
        }
        __syncthreads();

        #pragma unroll
        for (int kk = 0; kk < BK; kk++) {
            float a[TM], b[TN];
            float4 a0 = *(const float4*)&As[kk][ty * TM];
            float4 a1 = *(const float4*)&As[kk][ty * TM + 4];
            a[0] = a0.x; a[1] = a0.y; a[2] = a0.z; a[3] = a0.w;
            a[4] = a1.x; a[5] = a1.y; a[6] = a1.z; a[7] = a1.w;
            float4 b0 = *(const float4*)&Bs[kk][tx * TN];
            b[0] = b0.x; b[1] = b0.y; b[2] = b0.z; b[3] = b0.w;
            #pragma unroll
            for (int i = 0; i < TM; i++)
                #pragma unroll
                for (int j = 0; j < TN; j++)
                    acc[i][j] += a[i] * b[j];
        }
        __syncthreads();
    }

    #pragma unroll
    for (int i = 0; i < TM; i++) {
        int gr = rowBase + ty * TM + i;
        if (gr < M) {
            float4 v = make_float4(acc[i][0], acc[i][1], acc[i][2], acc[i][3]);
            *(float4*)&C[(long long)gr * Nn + colBase + tx * TN] = v;
        }
    }
}

// ---------------------------------------------------------------------------
// Aggregation
// ---------------------------------------------------------------------------

// out[v,f] = H[v,f] * dinv[v]^2   (self-loop contribution; writes ALL elements)
__global__ void selfinit_kernel(const float* __restrict__ H,
                                const float* __restrict__ dinv,
                                float* __restrict__ out, int C, int total)
{
    int i = blockIdx.x * blockDim.x + threadIdx.x;
    if (i >= total) return;
    int v = i / C;
    float w = dinv[v];
    out[i] = H[i] * w * w;
}

// For each edge (s,d): out[d,:] += H[s,:] * dinv[s]*dinv[d]
// One thread per (edge, feature); C is power of two.
__global__ void scatter_kernel(const float* __restrict__ H,
                               float* __restrict__ out,
                               const void* __restrict__ ei,
                               const float* __restrict__ dinv,
                               int E, int C)
{
    long long i = (long long)blockIdx.x * blockDim.x + threadIdx.x;
    long long total = (long long)E * C;
    if (i >= total) return;
    int e = (int)(i / C);
    int f = (int)(i - (long long)e * C);
    int is64 = g_is64;
    int s = edge_at(ei, e, is64);
    int d = edge_at(ei, (long long)E + e, is64);
    float w = dinv[s] * dinv[d];
    atomicAdd(&out[(long long)d * C + f], H[(long long)s * C + f] * w);
}

// A[i] = (relu ? max(A[i]+b[f],0) : A[i]+b[f])
__global__ void bias_kernel(float* __restrict__ A, const float* __restrict__ b,
                            int C, int total, int do_relu)
{
    int i = blockIdx.x * blockDim.x + threadIdx.x;
    if (i >= total) return;
    int f = i & (C - 1);
    float v = A[i] + b[f];
    if (do_relu) v = fmaxf(v, 0.0f);
    A[i] = v;
}

// ---------------------------------------------------------------------------
// Launch
// ---------------------------------------------------------------------------
extern "C" void kernel_launch(void* const* d_in, const int* in_sizes, int n_in,
                              void* d_out, int out_size)
{
    const float* x  = (const float*)d_in[0];
    const void*  ei = d_in[1];
    const float* W1 = (const float*)d_in[2];
    const float* b1 = (const float*)d_in[3];
    const float* W2 = (const float*)d_in[4];
    const float* b2 = (const float*)d_in[5];
    float* out = (float*)d_out;

    const int E = in_sizes[1] / 2;

    float *H1, *A1, *H2, *DEG, *DINV;
    cudaGetSymbolAddress((void**)&H1,   g_H1);
    cudaGetSymbolAddress((void**)&A1,   g_A1);
    cudaGetSymbolAddress((void**)&H2,   g_H2);
    cudaGetSymbolAddress((void**)&DEG,  g_DEG);
    cudaGetSymbolAddress((void**)&DINV, g_DINV);

    const int T = 256;

    // --- degree / normalization ---
    detect_kernel<<<1, 1>>>(ei, (long long)NNODES);
    zero_kernel<<<(NNODES + T - 1) / T, T>>>(DEG, NNODES);
    hist_kernel<<<(E + T - 1) / T, T>>>(ei, DEG, E);
    dinv_kernel<<<(NNODES + T - 1) / T, T>>>(DEG, DINV, NNODES);

    // --- layer 1 ---
    {
        dim3 grid(HID_C / 64, (NNODES + 127) / 128);
        gemm_kernel<<<grid, 256>>>(x, W1, H1, NNODES, IN_C, HID_C);
    }
    {
        int total = NNODES * HID_C;
        selfinit_kernel<<<(total + T - 1) / T, T>>>(H1, DINV, A1, HID_C, total);
        long long stotal = (long long)E * HID_C;
        scatter_kernel<<<(unsigned)((stotal + T - 1) / T), T>>>(H1, A1, ei, DINV, E, HID_C);
        bias_kernel<<<(total + T - 1) / T, T>>>(A1, b1, HID_C, total, 1);
    }

    // --- layer 2 ---
    {
        dim3 grid(OUT_C / 64, (NNODES + 127) / 128);
        gemm_kernel<<<grid, 256>>>(A1, W2, H2, NNODES, HID_C, OUT_C);
    }
    {
        int total = NNODES * OUT_C;
        selfinit_kernel<<<(total + T - 1) / T, T>>>(H2, DINV, out, OUT_C, total);
        long long stotal = (long long)E * OUT_C;
        scatter_kernel<<<(unsigned)((stotal + T - 1) / T), T>>>(H2, out, ei, DINV, E, OUT_C);
        bias_kernel<<<(total + T - 1) / T, T>>>(out, b2, OUT_C, total, 0);
    }
}

// round 2
// speedup vs baseline: 2.3543x; 2.3543x over previous
#include <cuda_runtime.h>
#include <cstdint>

#define NNODES 50000
#define MAXE   800000
#define IN_C   512
#define HID_C  256
#define OUT_C  128

// ---------------------------------------------------------------------------
// Scratch (device globals — allocation is forbidden)
// ---------------------------------------------------------------------------
__device__ float g_H1[(size_t)NNODES * HID_C];
__device__ float g_A1[(size_t)NNODES * HID_C];
__device__ float g_H2[(size_t)NNODES * OUT_C];
__device__ int   g_CNT[NNODES];
__device__ float g_DINV[NNODES];
__device__ int   g_ROWPTR[NNODES + 1];
__device__ int   g_CUR[NNODES];
__device__ int2  g_ADJ[MAXE];     // {src, bits(weight)}
__device__ int   g_is64;

// ---------------------------------------------------------------------------
// Edge index decoding (int64 vs int32, detected once per launch)
// ---------------------------------------------------------------------------
__device__ __forceinline__ int edge_at(const void* ei, long long i, int is64) {
    if (is64) return (int)((const long long*)ei)[i];
    return ((const int*)ei)[i];
}

__global__ void detect_kernel(const void* ei, long long maxv) {
    const long long* p = (const long long*)ei;
    int ok64 = 1;
    #pragma unroll
    for (int i = 0; i < 8; i++) {
        long long v = p[i];
        if (v < 0 || v >= maxv) ok64 = 0;
    }
    g_is64 = ok64;
}

// ---------------------------------------------------------------------------
// CSR build: histogram -> scan -> fill
// ---------------------------------------------------------------------------
__global__ void zero_cnt_kernel(int* p, int n) {
    int i = blockIdx.x * blockDim.x + threadIdx.x;
    if (i < n) p[i] = 0;
}

__global__ void hist_kernel(const void* __restrict__ ei, int* __restrict__ cnt, int E) {
    int e = blockIdx.x * blockDim.x + threadIdx.x;
    if (e >= E) return;
    int is64 = g_is64;
    int d = edge_at(ei, (long long)E + e, is64);
    atomicAdd(&cnt[d], 1);
}

__global__ void dinv_kernel(const int* __restrict__ cnt, float* __restrict__ dinv, int n) {
    int i = blockIdx.x * blockDim.x + threadIdx.x;
    if (i < n) dinv[i] = rsqrtf((float)cnt[i] + 1.0f);   // +1 self-loop
}

// Single-block exclusive scan over n (<=NNODES) ints; also writes cursor copy.
__global__ void scan_kernel(const int* __restrict__ cnt, int* __restrict__ rowptr,
                            int* __restrict__ cur, int n)
{
    __shared__ int sh[1024];
    __shared__ int carry_s;
    if (threadIdx.x == 0) carry_s = 0;
    __syncthreads();
    for (int base = 0; base < n; base += 1024) {
        int i = base + (int)threadIdx.x;
        int v = (i < n) ? cnt[i] : 0;
        sh[threadIdx.x] = v;
        __syncthreads();
        for (int off = 1; off < 1024; off <<= 1) {
            int t = (threadIdx.x >= off) ? sh[threadIdx.x - off] : 0;
            __syncthreads();
            sh[threadIdx.x] += t;
            __syncthreads();
        }
        int carry = carry_s;
        int excl = sh[threadIdx.x] - v + carry;
        if (i < n) { rowptr[i] = excl; cur[i] = excl; }
        __syncthreads();
        if (threadIdx.x == 1023) carry_s = carry + sh[1023];
        __syncthreads();
    }
    if (threadIdx.x == 0) rowptr[n] = carry_s;
}

__global__ void fill_kernel(const void* __restrict__ ei, const float* __restrict__ dinv,
                            int* __restrict__ cur, int2* __restrict__ adj, int E)
{
    int e = blockIdx.x * blockDim.x + threadIdx.x;
    if (e >= E) return;
    int is64 = g_is64;
    int s = edge_at(ei, e, is64);
    int d = edge_at(ei, (long long)E + e, is64);
    int pos = atomicAdd(&cur[d], 1);
    float w = dinv[s] * dinv[d];
    adj[pos] = make_int2(s, __float_as_int(w));
}

// ---------------------------------------------------------------------------
// Tiled fp32 GEMM: C = A[MxK] @ B[KxN], row-major.
// BM=BN=128, BK=8, 256 threads, 8x8 microtile with split-4 layout.
// Requires K%8==0, N%128==0 (true: 512/256, N=256/128). M guarded.
// ---------------------------------------------------------------------------
__global__ __launch_bounds__(256) void gemm_kernel(
    const float* __restrict__ A, const float* __restrict__ B,
    float* __restrict__ C, int M, int K, int Nn)
{
    const int BM = 128, BN = 128, BK = 8;
    __shared__ float As[BK][BM];
    __shared__ float Bs[BK][BN];

    const int tid = threadIdx.x;
    const int tx = tid & 15;        // N dim (16)
    const int ty = tid >> 4;        // M dim (16)
    const int rowBase = blockIdx.y * BM;
    const int colBase = blockIdx.x * BN;

    float acc[8][8];
    #pragma unroll
    for (int i = 0; i < 8; i++)
        #pragma unroll
        for (int j = 0; j < 8; j++) acc[i][j] = 0.0f;

    for (int k0 = 0; k0 < K; k0 += BK) {
        // A tile: 128 rows x 8 k = 256 float4s (1/thread)
        {
            int r  = tid >> 1;              // 0..127
            int kc = (tid & 1) * 4;         // 0 or 4
            float4 v = make_float4(0.f, 0.f, 0.f, 0.f);
            int gr = rowBase + r;
            if (gr < M) v = *(const float4*)&A[(size_t)gr * K + k0 + kc];
            As[kc + 0][r] = v.x;
            As[kc + 1][r] = v.y;
            As[kc + 2][r] = v.z;
            As[kc + 3][r] = v.w;
        }
        // B tile: 8 k x 128 cols = 256 float4s (1/thread)
        {
            int r = tid >> 5;               // 0..7
            int c = (tid & 31) * 4;         // 0..124
            *(float4*)&Bs[r][c] = *(const float4*)&B[(size_t)(k0 + r) * Nn + colBase + c];
        }
        __syncthreads();

        #pragma unroll
        for (int kk = 0; kk < BK; kk++) {
            float a[8], b[8];
            float4 a0 = *(const float4*)&As[kk][ty * 4];
            float4 a1 = *(const float4*)&As[kk][ty * 4 + 64];
            a[0]=a0.x; a[1]=a0.y; a[2]=a0.z; a[3]=a0.w;
            a[4]=a1.x; a[5]=a1.y; a[6]=a1.z; a[7]=a1.w;
            float4 b0 = *(const float4*)&Bs[kk][tx * 4];
            float4 b1 = *(const float4*)&Bs[kk][tx * 4 + 64];
            b[0]=b0.x; b[1]=b0.y; b[2]=b0.z; b[3]=b0.w;
            b[4]=b1.x; b[5]=b1.y; b[6]=b1.z; b[7]=b1.w;
            #pragma unroll
            for (int i = 0; i < 8; i++)
                #pragma unroll
                for (int j = 0; j < 8; j++)
                    acc[i][j] += a[i] * b[j];
        }
        __syncthreads();
    }

    #pragma unroll
    for (int i = 0; i < 8; i++) {
        int gr = rowBase + ty * 4 + (i < 4 ? i : 64 + i - 4);
        if (gr < M) {
            float4 v0 = make_float4(acc[i][0], acc[i][1], acc[i][2], acc[i][3]);
            float4 v1 = make_float4(acc[i][4], acc[i][5], acc[i][6], acc[i][7]);
            *(float4*)&C[(size_t)gr * Nn + colBase + tx * 4]      = v0;
            *(float4*)&C[(size_t)gr * Nn + colBase + tx * 4 + 64] = v1;
        }
    }
}

// ---------------------------------------------------------------------------
// CSR gather: out[v,:] = sum_{s in N(v)} H[s,:]*w(s,v) + H[v,:]*dinv[v]^2 + b
// One block per node, one thread per feature. Bias+ReLU fused.
// ---------------------------------------------------------------------------
template<int C, bool RELU>
__global__ __launch_bounds__(C) void gather_kernel(
    const float* __restrict__ H, const int* __restrict__ rowptr,
    const int2* __restrict__ adj, const float* __restrict__ dinv,
    const float* __restrict__ bias, float* __restrict__ out)
{
    int v = blockIdx.x;
    int f = threadIdx.x;
    float dv = dinv[v];
    float acc = H[(size_t)v * C + f] * dv * dv;

    int j   = rowptr[v];
    int end = rowptr[v + 1];
    // 2-way unroll for MLP
    for (; j + 1 < end; j += 2) {
        int2 a0 = __ldg(&adj[j]);
        int2 a1 = __ldg(&adj[j + 1]);
        float h0 = H[(size_t)a0.x * C + f];
        float h1 = H[(size_t)a1.x * C + f];
        acc += h0 * __int_as_float(a0.y);
        acc += h1 * __int_as_float(a1.y);
    }
    if (j < end) {
        int2 a0 = __ldg(&adj[j]);
        acc += H[(size_t)a0.x * C + f] * __int_as_float(a0.y);
    }

    acc += bias[f];
    if (RELU) acc = fmaxf(acc, 0.0f);
    out[(size_t)v * C + f] = acc;
}

// ---------------------------------------------------------------------------
// Launch
// ---------------------------------------------------------------------------
extern "C" void kernel_launch(void* const* d_in, const int* in_sizes, int n_in,
                              void* d_out, int out_size)
{
    const float* x  = (const float*)d_in[0];
    const void*  ei = d_in[1];
    const float* W1 = (const float*)d_in[2];
    const float* b1 = (const float*)d_in[3];
    const float* W2 = (const float*)d_in[4];
    const float* b2 = (const float*)d_in[5];
    float* out = (float*)d_out;

    const int E = in_sizes[1] / 2;

    float *H1, *A1, *H2, *DINV;
    int *CNT, *ROWPTR, *CUR;
    int2 *ADJ;
    cudaGetSymbolAddress((void**)&H1,     g_H1);
    cudaGetSymbolAddress((void**)&A1,     g_A1);
    cudaGetSymbolAddress((void**)&H2,     g_H2);
    cudaGetSymbolAddress((void**)&CNT,    g_CNT);
    cudaGetSymbolAddress((void**)&DINV,   g_DINV);
    cudaGetSymbolAddress((void**)&ROWPTR, g_ROWPTR);
    cudaGetSymbolAddress((void**)&CUR,    g_CUR);
    cudaGetSymbolAddress((void**)&ADJ,    g_ADJ);

    const int T = 256;

    // --- CSR build ---
    detect_kernel<<<1, 1>>>(ei, (long long)NNODES);
    zero_cnt_kernel<<<(NNODES + T - 1) / T, T>>>(CNT, NNODES);
    hist_kernel<<<(E + T - 1) / T, T>>>(ei, CNT, E);
    dinv_kernel<<<(NNODES + T - 1) / T, T>>>(CNT, DINV, NNODES);
    scan_kernel<<<1, 1024>>>(CNT, ROWPTR, CUR, NNODES);
    fill_kernel<<<(E + T - 1) / T, T>>>(ei, DINV, CUR, ADJ, E);

    // --- layer 1: H1 = x@W1 ; A1 = Agg(H1) + b1, relu ---
    {
        dim3 grid(HID_C / 128, (NNODES + 127) / 128);
        gemm_kernel<<<grid, 256>>>(x, W1, H1, NNODES, IN_C, HID_C);
        gather_kernel<HID_C, true><<<NNODES, HID_C>>>(H1, ROWPTR, ADJ, DINV, b1, A1);
    }

    // --- layer 2: H2 = A1@W2 ; out = Agg(H2) + b2 ---
    {
        dim3 grid(OUT_C / 128, (NNODES + 127) / 128);
        gemm_kernel<<<grid, 256>>>(A1, W2, H2, NNODES, HID_C, OUT_C);
        gather_kernel<OUT_C, false><<<NNODES, OUT_C>>>(H2, ROWPTR, ADJ, DINV, b2, out);
    }
}